// round 2
// baseline (speedup 1.0000x reference)
#include <cuda_runtime.h>
#include <math.h>
#include <stdint.h>

// Problem constants (fixed by the reference)
#define B_    64
#define H_    1024
#define E_    512
#define S_    400
#define V_    50000
#define NOOV_ 100
#define EXT_  (V_ + NOOV_)   // 50100

// ---------------- device scratch (no allocs allowed) ----------------
__device__ float g_mid[B_ * H_];     // tanh hidden, [64, 1024]
__device__ float g_pgen[B_];         // p_gen per row
__device__ float g_rowsum[B_];       // softmax denominators (unnormalized exp sums)

// ---------------- helpers ----------------
__device__ __forceinline__ unsigned f2tf32(float f) {
    unsigned u;
    asm("cvt.rna.tf32.f32 %0, %1;" : "=r"(u) : "f"(f));
    return u;
}

__device__ __forceinline__ void mma_tf32(float& c0, float& c1, float& c2, float& c3,
                                         unsigned a0, unsigned a1, unsigned a2, unsigned a3,
                                         unsigned b0, unsigned b1) {
    asm volatile(
        "mma.sync.aligned.m16n8k8.row.col.f32.tf32.tf32.f32 "
        "{%0,%1,%2,%3}, {%4,%5,%6,%7}, {%8,%9}, {%0,%1,%2,%3};\n"
        : "+f"(c0), "+f"(c1), "+f"(c2), "+f"(c3)
        : "r"(a0), "r"(a1), "r"(a2), "r"(a3), "r"(b0), "r"(b1));
}

// ============================================================================
// Fused GEMM:  C[64, N] = act( A[64, K] @ W[N, K]^T + bias )
//   A may be split into two row-major pieces A0 (cols [0,Ksplit)) and
//   A1 (cols [Ksplit, K)) to realize concat([dec, ctx]) without a copy.
//   A0 == nullptr means "use g_mid" (Ksplit must equal K then).
// EPI == 0 : act = tanh, write to g_mid              (N = H_)
// EPI == 1 : act = exp(clip(.,±50)), write unnormalized exp to outE [64, N],
//            accumulate per-row sums into g_rowsum   (N = V_)
// Block: 256 threads (8 warps), BM=64 (whole M), BN=64, BK=32, tf32 MMA.
// Warp grid: 4 (M, 16 rows each) x 2 (N, 32 cols each).
// ============================================================================
template <int EPI>
__global__ void __launch_bounds__(256)
gemm_fused_kernel(const float* __restrict__ A0, const float* __restrict__ A1,
                  int Ksplit, const float* __restrict__ W,
                  const float* __restrict__ bias, int N, int K,
                  float* __restrict__ outE)
{
    constexpr int BM = 64, BN = 64, BK = 32, LDSH = 36;  // 36-word stride: 144B, 16B-aligned
    __shared__ unsigned As[BM * LDSH];
    __shared__ unsigned Bs[BN * LDSH];

    const int tid  = threadIdx.x;
    const int warp = tid >> 5;
    const int lane = tid & 31;
    const int wm   = warp & 3;   // M warp tile (16 rows)
    const int wn   = warp >> 2;  // N warp tile (32 cols)
    const int gid  = lane >> 2;  // group id (0..7)
    const int tig  = lane & 3;   // thread in group (0..3)
    const int n0   = blockIdx.x * BN;

    const float* Abase0 = (A0 != nullptr) ? A0 : g_mid;

    float c[4][4];
#pragma unroll
    for (int j = 0; j < 4; j++)
#pragma unroll
        for (int r = 0; r < 4; r++) c[j][r] = 0.f;

    for (int k0 = 0; k0 < K; k0 += BK) {
        // ---- stage A tile [64 x 32] ----
        {
            const float* Asrc;
            int koff, strideA;
            if (k0 < Ksplit) { Asrc = Abase0; koff = k0;          strideA = Ksplit; }
            else             { Asrc = A1;     koff = k0 - Ksplit; strideA = K - Ksplit; }
            int id = tid * 2;
#pragma unroll
            for (int u = 0; u < 2; u++, id++) {
                int row = id >> 3;
                int c4  = (id & 7) * 4;
                float4 v = *reinterpret_cast<const float4*>(Asrc + (size_t)row * strideA + koff + c4);
                uint4 t;
                t.x = f2tf32(v.x); t.y = f2tf32(v.y); t.z = f2tf32(v.z); t.w = f2tf32(v.w);
                *reinterpret_cast<uint4*>(&As[row * LDSH + c4]) = t;
            }
        }
        // ---- stage B tile: W rows [n0, n0+64), cols [k0, k0+32) ----
        {
            int id = tid * 2;
#pragma unroll
            for (int u = 0; u < 2; u++, id++) {
                int row = id >> 3;
                int c4  = (id & 7) * 4;
                int n   = n0 + row;
                float4 v;
                if (n < N) v = *reinterpret_cast<const float4*>(W + (size_t)n * K + k0 + c4);
                else       v = make_float4(0.f, 0.f, 0.f, 0.f);
                uint4 t;
                t.x = f2tf32(v.x); t.y = f2tf32(v.y); t.z = f2tf32(v.z); t.w = f2tf32(v.w);
                *reinterpret_cast<uint4*>(&Bs[row * LDSH + c4]) = t;
            }
        }
        __syncthreads();

        // ---- compute: 4 K-steps of 8 ----
#pragma unroll
        for (int kk = 0; kk < BK; kk += 8) {
            const int arow = wm * 16 + gid;
            unsigned a0 = As[arow * LDSH + kk + tig];
            unsigned a1 = As[(arow + 8) * LDSH + kk + tig];
            unsigned a2 = As[arow * LDSH + kk + tig + 4];
            unsigned a3 = As[(arow + 8) * LDSH + kk + tig + 4];
#pragma unroll
            for (int j = 0; j < 4; j++) {
                const int bn = wn * 32 + j * 8 + gid;
                unsigned b0 = Bs[bn * LDSH + kk + tig];
                unsigned b1 = Bs[bn * LDSH + kk + tig + 4];
                mma_tf32(c[j][0], c[j][1], c[j][2], c[j][3], a0, a1, a2, a3, b0, b1);
            }
        }
        __syncthreads();
    }

    // ---- epilogue ----
    if (EPI == 0) {
        // tanh -> g_mid
#pragma unroll
        for (int j = 0; j < 4; j++)
#pragma unroll
            for (int r = 0; r < 4; r++) {
                int col = n0 + wn * 32 + j * 8 + tig * 2 + (r & 1);
                int row = wm * 16 + gid + ((r >= 2) ? 8 : 0);
                if (col < N)
                    g_mid[row * H_ + col] = tanhf(c[j][r] + bias[col]);
            }
    } else {
        // exp(clip) -> outE (unnormalized), row-sum atomics
        float rs0 = 0.f, rs1 = 0.f;
#pragma unroll
        for (int j = 0; j < 4; j++)
#pragma unroll
            for (int r = 0; r < 4; r++) {
                int col = n0 + wn * 32 + j * 8 + tig * 2 + (r & 1);
                if (col < N) {
                    int row = wm * 16 + gid + ((r >= 2) ? 8 : 0);
                    float v = c[j][r] + bias[col];
                    v = fminf(fmaxf(v, -50.f), 50.f);
                    float e = expf(v);
                    outE[(size_t)row * N + col] = e;
                    if (r < 2) rs0 += e; else rs1 += e;
                }
            }
        // reduce across the 4 lanes of each group (same output rows)
        rs0 += __shfl_xor_sync(0xffffffffu, rs0, 1);
        rs0 += __shfl_xor_sync(0xffffffffu, rs0, 2);
        rs1 += __shfl_xor_sync(0xffffffffu, rs1, 1);
        rs1 += __shfl_xor_sync(0xffffffffu, rs1, 2);
        if (tig == 0) {
            atomicAdd(&g_rowsum[wm * 16 + gid],     rs0);
            atomicAdd(&g_rowsum[wm * 16 + gid + 8], rs1);
        }
    }
}

// ============================================================================
// p_gen = sigmoid([dec;ctx;emb] @ W_pgen^T + b_pgen); also zeroes g_rowsum
// (per-launch re-init keeps graph replays deterministic).
// ============================================================================
__global__ void pgen_kernel(const float* __restrict__ dec, const float* __restrict__ ctx,
                            const float* __restrict__ emb, const float* __restrict__ Wp,
                            const float* __restrict__ bp, float* __restrict__ out_pgen)
{
    const int warp = threadIdx.x >> 5;
    const int lane = threadIdx.x & 31;
    if (threadIdx.x < B_) g_rowsum[threadIdx.x] = 0.f;

    for (int b = warp; b < B_; b += 8) {
        float s = 0.f;
        for (int k = lane; k < 2 * H_ + E_; k += 32) {
            float x;
            if (k < H_)           x = dec[b * H_ + k];
            else if (k < 2 * H_)  x = ctx[b * H_ + k - H_];
            else                  x = emb[b * E_ + k - 2 * H_];
            s += x * Wp[k];
        }
#pragma unroll
        for (int off = 16; off; off >>= 1) s += __shfl_xor_sync(0xffffffffu, s, off);
        if (lane == 0) {
            float p = 1.f / (1.f + expf(-(s + bp[0])));
            g_pgen[b]  = p;
            out_pgen[b] = p;
        }
    }
}

// ============================================================================
// Normalize vocab_dist in place; build final_dist = p_gen * vocab_dist and
// zero the OOV tail [V, EXT).  EXT_/4 = 12525 exactly, so float4 covers all.
// grid: (ceil(12525/256), 64)
// ============================================================================
__global__ void norm_kernel(float* __restrict__ d_final, float* __restrict__ d_vocab)
{
    const int row = blockIdx.y;
    const int c4  = blockIdx.x * blockDim.x + threadIdx.x;  // float4 index
    const float inv = 1.f / g_rowsum[row];
    const float pg  = g_pgen[row];

    if (c4 < V_ / 4) {
        float4 v = *reinterpret_cast<float4*>(d_vocab + (size_t)row * V_ + c4 * 4);
        v.x *= inv; v.y *= inv; v.z *= inv; v.w *= inv;
        *reinterpret_cast<float4*>(d_vocab + (size_t)row * V_ + c4 * 4) = v;
        float4 f = make_float4(v.x * pg, v.y * pg, v.z * pg, v.w * pg);
        *reinterpret_cast<float4*>(d_final + (size_t)row * EXT_ + c4 * 4) = f;
    } else if (c4 < EXT_ / 4) {
        *reinterpret_cast<float4*>(d_final + (size_t)row * EXT_ + c4 * 4) =
            make_float4(0.f, 0.f, 0.f, 0.f);
    }
}

// ============================================================================
// Copy distribution scatter: final[b, idx] += (1 - p_gen[b]) * attn[b, s]
// ============================================================================
__global__ void scatter_kernel(const float* __restrict__ attn, const int* __restrict__ src_ids,
                               const int* __restrict__ oov, float* __restrict__ d_final)
{
    const int i = blockIdx.x * blockDim.x + threadIdx.x;
    if (i >= B_ * S_) return;
    const int b = i / S_;
    const int m = oov[i];
    const int idx = (m >= 0) ? (V_ + m) : src_ids[i];
    const float w = attn[i] * (1.f - g_pgen[b]);
    atomicAdd(d_final + (size_t)b * EXT_ + idx, w);
}

// ============================================================================
// kernel_launch
// Inputs (metadata order): decoder_output, context, embedded, attn_weights,
//   src_ids, src_oov_map, [vocab_size scalar?], W_mid, b_mid, W_pgen, b_pgen,
//   W_vocab, b_vocab
// Output: concat(final_dist [64,50100], p_gen [64], vocab_dist [64,50000])
// ============================================================================
extern "C" void kernel_launch(void* const* d_in, const int* in_sizes, int n_in,
                              void* d_out, int out_size)
{
    const float* dec    = (const float*)d_in[0];
    const float* ctx    = (const float*)d_in[1];
    const float* emb    = (const float*)d_in[2];
    const float* attn   = (const float*)d_in[3];
    const int*   srcids = (const int*)d_in[4];
    const int*   oov    = (const int*)d_in[5];

    // vocab_size may or may not materialize as a device input
    int base = 6;
    if (n_in >= 13 && in_sizes[6] == 1) base = 7;
    const float* Wm = (const float*)d_in[base + 0];
    const float* bm = (const float*)d_in[base + 1];
    const float* Wp = (const float*)d_in[base + 2];
    const float* bp = (const float*)d_in[base + 3];
    const float* Wv = (const float*)d_in[base + 4];
    const float* bv = (const float*)d_in[base + 5];

    float* out     = (float*)d_out;
    float* d_final = out;                              // [64, 50100]
    float* d_pgen  = out + (size_t)B_ * EXT_;          // [64]
    float* d_vocab = d_pgen + B_;                      // [64, 50000]

    // 1) p_gen + zero row sums
    pgen_kernel<<<1, 256>>>(dec, ctx, emb, Wp, bp, d_pgen);

    // 2) mid = tanh([dec;ctx] @ W_mid^T + b_mid)  (M=64, N=1024, K=2048)
    gemm_fused_kernel<0><<<H_ / 64, 256>>>(dec, ctx, H_, Wm, bm, H_, 2 * H_, nullptr);

    // 3) vocab logits -> exp + row sums  (M=64, N=50000, K=1024)
    gemm_fused_kernel<1><<<(V_ + 63) / 64, 256>>>(nullptr, nullptr, H_, Wv, bv, V_, H_, d_vocab);

    // 4) normalize + assemble generator part of final_dist (+ zero OOV tail)
    dim3 ngrid((EXT_ / 4 + 255) / 256, B_);
    norm_kernel<<<ngrid, 256>>>(d_final, d_vocab);

    // 5) copy-scatter
    scatter_kernel<<<(B_ * S_ + 255) / 256, 256>>>(attn, srcids, oov, d_final);
}

// round 6
// speedup vs baseline: 1.2542x; 1.2542x over previous
#include <cuda_runtime.h>
#include <math.h>
#include <stdint.h>

// Problem constants (fixed by the reference)
#define B_    64
#define H_    1024
#define E_    512
#define S_    400
#define V_    50000
#define NOOV_ 100
#define EXT_  (V_ + NOOV_)   // 50100

// ---------------- device scratch (no allocs allowed) ----------------
__device__ float g_mid[B_ * H_];     // tanh hidden, [64, 1024]
__device__ float g_pgen[B_];         // p_gen per row
__device__ float g_rowsum[B_];       // softmax denominators

// ---------------- helpers ----------------
__device__ __forceinline__ uint32_t cvta_s(const void* p) {
    return (uint32_t)__cvta_generic_to_shared(p);
}
__device__ __forceinline__ void cp_async16(uint32_t saddr, const void* g) {
    asm volatile("cp.async.cg.shared.global [%0], [%1], 16;\n" :: "r"(saddr), "l"(g));
}
__device__ __forceinline__ void cp_commit() { asm volatile("cp.async.commit_group;\n"); }
template <int N>
__device__ __forceinline__ void cp_wait() { asm volatile("cp.async.wait_group %0;\n" :: "n"(N)); }

// tf32 MMA; operands are raw f32 bit patterns (HW truncates to tf32 = RZ)
__device__ __forceinline__ void mma_tf32(float& c0, float& c1, float& c2, float& c3,
                                         unsigned a0, unsigned a1, unsigned a2, unsigned a3,
                                         unsigned b0, unsigned b1) {
    asm volatile(
        "mma.sync.aligned.m16n8k8.row.col.f32.tf32.tf32.f32 "
        "{%0,%1,%2,%3}, {%4,%5,%6,%7}, {%8,%9}, {%0,%1,%2,%3};\n"
        : "+f"(c0), "+f"(c1), "+f"(c2), "+f"(c3)
        : "r"(a0), "r"(a1), "r"(a2), "r"(a3), "r"(b0), "r"(b1));
}

// ============================================================================
// Pipelined fused GEMM:  C[64, N] = act( A[64, K] @ W[N, K]^T + bias )
//   3-stage cp.async pipeline, BM=64, BN=NJ*32 (4 N-warps x (NJ*8) cols each),
//   BK=32, 256 threads. Warp grid: 2 (M, 32 rows) x 4 (N, WNT=NJ*8 cols).
//   A split [A0 | A1] at Ksplit (concat w/o copy); A0==nullptr -> g_mid.
// EPI 0: tanh -> g_mid.   EPI 1: exp(clip +-50) -> outE, row sums -> g_rowsum.
// ============================================================================
template <int EPI, int NJ>
__global__ void __launch_bounds__(256)
gemm_pipe(const float* __restrict__ A0, const float* __restrict__ A1, int Ksplit,
          const float* __restrict__ W, const float* __restrict__ bias,
          int N, int K, float* __restrict__ outE)
{
    constexpr int BM = 64, BK = 32, LDSH = 36, STAGES = 3;
    constexpr int BN  = NJ * 32;
    constexpr int WNT = NJ * 8;       // per-warp N tile (4 N-warps cover BN)
    constexpr int ASTG = BM * LDSH;   // floats per A stage
    constexpr int BSTG = BN * LDSH;   // floats per B stage

    extern __shared__ float smem[];
    float* Asm = smem;                   // [STAGES][ASTG]
    float* Bsm = smem + STAGES * ASTG;   // [STAGES][BSTG]

    const int tid  = threadIdx.x;
    const int warp = tid >> 5;
    const int lane = tid & 31;
    const int wm   = warp & 1;    // M half (32 rows)
    const int wn   = warp >> 1;   // N quarter (WNT cols)
    const int gid  = lane >> 2;
    const int tig  = lane & 3;
    const int n0   = blockIdx.x * BN;
    const int KI   = K / BK;

    const float* Ab0 = (A0 != nullptr) ? A0 : g_mid;

    // ---- stage loader: 2 A-chunks + NJ B-chunks of 16B per thread ----
    auto stage_load = [&](int s, int k0) {
        const float* Asrc; int koff, strideA;
        if (k0 < Ksplit) { Asrc = Ab0; koff = k0;          strideA = Ksplit; }
        else             { Asrc = A1;  koff = k0 - Ksplit; strideA = K - Ksplit; }
        float* As = Asm + s * ASTG;
        float* Bs = Bsm + s * BSTG;
#pragma unroll
        for (int u = 0; u < 2; u++) {
            int ch = tid + u * 256;
            int row = ch >> 3, c4 = (ch & 7) * 4;
            cp_async16(cvta_s(&As[row * LDSH + c4]),
                       Asrc + (size_t)row * strideA + koff + c4);
        }
#pragma unroll
        for (int u = 0; u < NJ; u++) {
            int ch = tid + u * 256;
            int row = ch >> 3, c4 = (ch & 7) * 4;
            int n = n0 + row; n = (n < N) ? n : (N - 1);   // clamp: valid addr, junk ok
            cp_async16(cvta_s(&Bs[row * LDSH + c4]),
                       W + (size_t)n * K + k0 + c4);
        }
        cp_commit();
    };

    float c[2][NJ][4];
#pragma unroll
    for (int mi = 0; mi < 2; mi++)
#pragma unroll
        for (int nj = 0; nj < NJ; nj++)
#pragma unroll
            for (int r = 0; r < 4; r++) c[mi][nj][r] = 0.f;

    // ---- prologue: fill STAGES-1 stages (group j <-> stage j) ----
    stage_load(0, 0);
    stage_load(1, BK);

    // ---- mainloop ----
    // Invariant: at top of iter i, groups 0..i+1 committed. wait<1> => 0..i done.
    for (int i = 0; i < KI; i++) {
        cp_wait<1>();
        __syncthreads();       // all warps done reading buffer (i+2)%3's old data
        if (i + 2 < KI) stage_load((i + 2) % STAGES, (i + 2) * BK);
        else            cp_commit();   // empty group keeps the wait invariant

        const float* As = Asm + (i % STAGES) * ASTG;
        const float* Bs = Bsm + (i % STAGES) * BSTG;
#pragma unroll
        for (int kk = 0; kk < BK; kk += 8) {
            unsigned a[2][4];
#pragma unroll
            for (int mi = 0; mi < 2; mi++) {
                int ar = wm * 32 + mi * 16 + gid;
                a[mi][0] = __float_as_uint(As[ar * LDSH + kk + tig]);
                a[mi][1] = __float_as_uint(As[(ar + 8) * LDSH + kk + tig]);
                a[mi][2] = __float_as_uint(As[ar * LDSH + kk + tig + 4]);
                a[mi][3] = __float_as_uint(As[(ar + 8) * LDSH + kk + tig + 4]);
            }
#pragma unroll
            for (int nj = 0; nj < NJ; nj++) {
                int bn = wn * WNT + nj * 8 + gid;
                unsigned b0 = __float_as_uint(Bs[bn * LDSH + kk + tig]);
                unsigned b1 = __float_as_uint(Bs[bn * LDSH + kk + tig + 4]);
#pragma unroll
                for (int mi = 0; mi < 2; mi++)
                    mma_tf32(c[mi][nj][0], c[mi][nj][1], c[mi][nj][2], c[mi][nj][3],
                             a[mi][0], a[mi][1], a[mi][2], a[mi][3], b0, b1);
            }
        }
        // next iteration's top __syncthreads protects buffer reuse
    }

    // ---- epilogue ----
    if (EPI == 0) {
        // tanh -> g_mid, float2 stores (cols tig*2, tig*2+1 adjacent)
#pragma unroll
        for (int mi = 0; mi < 2; mi++)
#pragma unroll
            for (int nj = 0; nj < NJ; nj++)
#pragma unroll
                for (int hi = 0; hi < 2; hi++) {
                    int row = wm * 32 + mi * 16 + gid + hi * 8;
                    int col = n0 + wn * WNT + nj * 8 + tig * 2;
                    if (col < N) {
                        float2 v;
                        v.x = tanhf(c[mi][nj][2 * hi]     + bias[col]);
                        v.y = tanhf(c[mi][nj][2 * hi + 1] + bias[col + 1]);
                        *reinterpret_cast<float2*>(&g_mid[row * H_ + col]) = v;
                    }
                }
    } else {
        float rs[2][2] = {{0.f, 0.f}, {0.f, 0.f}};
#pragma unroll
        for (int mi = 0; mi < 2; mi++)
#pragma unroll
            for (int nj = 0; nj < NJ; nj++)
#pragma unroll
                for (int hi = 0; hi < 2; hi++) {
                    int row = wm * 32 + mi * 16 + gid + hi * 8;
                    int col = n0 + wn * WNT + nj * 8 + tig * 2;
                    if (col < N) {
                        float v0 = c[mi][nj][2 * hi]     + bias[col];
                        float v1 = c[mi][nj][2 * hi + 1] + bias[col + 1];
                        v0 = fminf(fmaxf(v0, -50.f), 50.f);
                        v1 = fminf(fmaxf(v1, -50.f), 50.f);
                        float e0 = expf(v0), e1 = expf(v1);
                        *reinterpret_cast<float2*>(&outE[(size_t)row * N + col]) =
                            make_float2(e0, e1);
                        rs[mi][hi] += e0 + e1;
                    }
                }
        // reduce over the 4 tig lanes (same rows)
#pragma unroll
        for (int mi = 0; mi < 2; mi++)
#pragma unroll
            for (int hi = 0; hi < 2; hi++) {
                rs[mi][hi] += __shfl_xor_sync(0xffffffffu, rs[mi][hi], 1);
                rs[mi][hi] += __shfl_xor_sync(0xffffffffu, rs[mi][hi], 2);
            }
        // block-level smem reduction, then 64 global atomics per block
        __syncthreads();                  // all warps done with stage buffers
        float* red = smem;                // reuse
        if (tid < BM) red[tid] = 0.f;
        __syncthreads();
        if (tig == 0) {
#pragma unroll
            for (int mi = 0; mi < 2; mi++)
#pragma unroll
                for (int hi = 0; hi < 2; hi++)
                    atomicAdd(&red[wm * 32 + mi * 16 + gid + hi * 8], rs[mi][hi]);
        }
        __syncthreads();
        if (tid < BM) atomicAdd(&g_rowsum[tid], red[tid]);
    }
}

// ============================================================================
// p_gen = sigmoid([dec;ctx;emb] @ W_pgen^T + b_pgen); zeroes g_rowsum
// (per-launch re-init keeps graph replays deterministic).
// ============================================================================
__global__ void pgen_kernel(const float* __restrict__ dec, const float* __restrict__ ctx,
                            const float* __restrict__ emb, const float* __restrict__ Wp,
                            const float* __restrict__ bp, float* __restrict__ out_pgen)
{
    const int warp = threadIdx.x >> 5;
    const int lane = threadIdx.x & 31;
    if (threadIdx.x < B_) g_rowsum[threadIdx.x] = 0.f;

    for (int b = warp; b < B_; b += 8) {
        float s = 0.f;
        for (int k = lane; k < 2 * H_ + E_; k += 32) {
            float x;
            if (k < H_)           x = dec[b * H_ + k];
            else if (k < 2 * H_)  x = ctx[b * H_ + k - H_];
            else                  x = emb[b * E_ + k - 2 * H_];
            s += x * Wp[k];
        }
#pragma unroll
        for (int off = 16; off; off >>= 1) s += __shfl_xor_sync(0xffffffffu, s, off);
        if (lane == 0) {
            float p = 1.f / (1.f + expf(-(s + bp[0])));
            g_pgen[b]  = p;
            out_pgen[b] = p;
        }
    }
}

// ============================================================================
// Normalize vocab_dist in place; final_dist = p_gen * vocab_dist; zero OOV tail.
// ============================================================================
__global__ void norm_kernel(float* __restrict__ d_final, float* __restrict__ d_vocab)
{
    const int row = blockIdx.y;
    const int c4  = blockIdx.x * blockDim.x + threadIdx.x;
    const float inv = 1.f / g_rowsum[row];
    const float pg  = g_pgen[row];

    if (c4 < V_ / 4) {
        float4 v = *reinterpret_cast<float4*>(d_vocab + (size_t)row * V_ + c4 * 4);
        v.x *= inv; v.y *= inv; v.z *= inv; v.w *= inv;
        *reinterpret_cast<float4*>(d_vocab + (size_t)row * V_ + c4 * 4) = v;
        float4 f = make_float4(v.x * pg, v.y * pg, v.z * pg, v.w * pg);
        *reinterpret_cast<float4*>(d_final + (size_t)row * EXT_ + c4 * 4) = f;
    } else if (c4 < EXT_ / 4) {
        *reinterpret_cast<float4*>(d_final + (size_t)row * EXT_ + c4 * 4) =
            make_float4(0.f, 0.f, 0.f, 0.f);
    }
}

// ============================================================================
// Copy scatter: final[b, idx] += (1 - p_gen[b]) * attn[b, s]
// ============================================================================
__global__ void scatter_kernel(const float* __restrict__ attn, const int* __restrict__ src_ids,
                               const int* __restrict__ oov, float* __restrict__ d_final)
{
    const int i = blockIdx.x * blockDim.x + threadIdx.x;
    if (i >= B_ * S_) return;
    const int b = i / S_;
    const int m = oov[i];
    const int idx = (m >= 0) ? (V_ + m) : src_ids[i];
    const float w = attn[i] * (1.f - g_pgen[b]);
    atomicAdd(d_final + (size_t)b * EXT_ + idx, w);
}

// ============================================================================
// kernel_launch
// Inputs: decoder_output, context, embedded, attn_weights, src_ids, src_oov_map,
//   [vocab_size?], W_mid, b_mid, W_pgen, b_pgen, W_vocab, b_vocab
// Output: concat(final_dist [64,50100], p_gen [64], vocab_dist [64,50000])
// ============================================================================
extern "C" void kernel_launch(void* const* d_in, const int* in_sizes, int n_in,
                              void* d_out, int out_size)
{
    const float* dec    = (const float*)d_in[0];
    const float* ctx    = (const float*)d_in[1];
    const float* emb    = (const float*)d_in[2];
    const float* attn   = (const float*)d_in[3];
    const int*   srcids = (const int*)d_in[4];
    const int*   oov    = (const int*)d_in[5];

    int base = 6;
    if (n_in >= 13 && in_sizes[6] == 1) base = 7;
    const float* Wm = (const float*)d_in[base + 0];
    const float* bm = (const float*)d_in[base + 1];
    const float* Wp = (const float*)d_in[base + 2];
    const float* bp = (const float*)d_in[base + 3];
    const float* Wv = (const float*)d_in[base + 4];
    const float* bv = (const float*)d_in[base + 5];

    float* out     = (float*)d_out;
    float* d_final = out;                              // [64, 50100]
    float* d_pgen  = out + (size_t)B_ * EXT_;          // [64]
    float* d_vocab = d_pgen + B_;                      // [64, 50000]

    // dynamic smem: STAGES * (BM + BN) * LDSH * 4B
    const int SMEM_MID = 3 * (64 + 64)  * 36 * 4;   // 55296
    const int SMEM_VOC = 3 * (64 + 128) * 36 * 4;   // 82944
    cudaFuncSetAttribute(gemm_pipe<0, 2>, cudaFuncAttributeMaxDynamicSharedMemorySize, SMEM_MID);
    cudaFuncSetAttribute(gemm_pipe<1, 4>, cudaFuncAttributeMaxDynamicSharedMemorySize, SMEM_VOC);

    // 1) p_gen + zero row sums
    pgen_kernel<<<1, 256>>>(dec, ctx, emb, Wp, bp, d_pgen);

    // 2) mid = tanh([dec;ctx] @ W_mid^T + b_mid)  (M=64, N=1024, K=2048), BN=64
    gemm_pipe<0, 2><<<H_ / 64, 256, SMEM_MID>>>(dec, ctx, H_, Wm, bm, H_, 2 * H_, nullptr);

    // 3) vocab: exp(clip(logits)) + row sums  (M=64, N=50000, K=1024), BN=128
    gemm_pipe<1, 4><<<(V_ + 127) / 128, 256, SMEM_VOC>>>(nullptr, nullptr, H_, Wv, bv,
                                                         V_, H_, d_vocab);

    // 4) normalize + generator part of final_dist (+ zero OOV tail)
    dim3 ngrid((EXT_ / 4 + 255) / 256, B_);
    norm_kernel<<<ngrid, 256>>>(d_final, d_vocab);

    // 5) copy-scatter
    scatter_kernel<<<(B_ * S_ + 255) / 256, 256>>>(attn, srcids, oov, d_final);
}